// round 2
// baseline (speedup 1.0000x reference)
#include <cuda_runtime.h>
#include <math.h>

#define NNODES 50000
#define DEGC 16

// ---------------- scratch (device globals; no runtime allocation) ----------
// g_feat layout per node (256 floats): [0..63]=z, [64..191]=Wh, [192..193]=el(h0,h1), [194..195]=er(h0,h1)
__device__ float g_feat[NNODES * 256];
__device__ float g_gated[NNODES * 128];
__device__ float g_meso[NNODES * 64];
__device__ float g_vlr[128 * 4];   // [k][el0,el1,er0,er1]

__device__ __forceinline__ float sigmoidf_(float v) { return 1.f / (1.f + __expf(-v)); }

// ---------------- K0: fold attn_l / attn_r into Wfc (128x4 vectors) --------
__global__ void k0_fold_attn(const float* __restrict__ Wfc,
                             const float* __restrict__ al,
                             const float* __restrict__ ar) {
    int k = threadIdx.x;  // 128 threads
#pragma unroll
    for (int h = 0; h < 2; ++h) {
        float sl = 0.f, sr = 0.f;
#pragma unroll 8
        for (int q = 0; q < 64; ++q) {
            float w = Wfc[k * 128 + h * 64 + q];
            sl += w * al[h * 64 + q];
            sr += w * ar[h * 64 + q];
        }
        g_vlr[k * 4 + h] = sl;
        g_vlr[k * 4 + 2 + h] = sr;
    }
}

// ---------------- K1: per-node linears: z = x@Wm+bm ; Wh = x@Wfc ; el/er ---
// 64-node tile, 256 threads (16x16), 4x4 register micro-tile, K=128.
__global__ void k1_node_linear(const float* __restrict__ x,
                               const float* __restrict__ Wm,
                               const float* __restrict__ bm,
                               const float* __restrict__ Wfc) {
    extern __shared__ float sm[];
    float(*xs)[68] = (float(*)[68])sm;              // [128][68]  x tile, k-major
    float(*ws)[68] = (float(*)[68])(sm + 128 * 68); // [128][68]  weight tile
    const int tid = threadIdx.x;
    const int tx = tid & 15, ty = tid >> 4;
    const int n0 = blockIdx.x * 64;

    for (int idx = tid; idx < 64 * 128; idx += 256) {
        int nn = idx >> 7, k = idx & 127;
        int node = n0 + nn;
        xs[k][nn] = (node < NNODES) ? x[node * 128 + k] : 0.f;
    }

    for (int pass = 0; pass < 3; ++pass) {
        __syncthreads();
        if (pass == 0) {
            for (int idx = tid; idx < 128 * 64; idx += 256) {
                int k = idx >> 6, c = idx & 63;
                ws[k][c] = Wm[k * 64 + c];
            }
        } else {
            int coff = (pass - 1) * 64;
            for (int idx = tid; idx < 128 * 64; idx += 256) {
                int k = idx >> 6, c = idx & 63;
                ws[k][c] = Wfc[k * 128 + coff + c];
            }
        }
        __syncthreads();

        float acc[4][4] = {};
#pragma unroll 4
        for (int k = 0; k < 128; ++k) {
            float4 a4 = *(const float4*)&xs[k][ty * 4];
            float4 b4 = *(const float4*)&ws[k][tx * 4];
            float av[4] = {a4.x, a4.y, a4.z, a4.w};
            float bv[4] = {b4.x, b4.y, b4.z, b4.w};
#pragma unroll
            for (int i = 0; i < 4; ++i)
#pragma unroll
                for (int j = 0; j < 4; ++j) acc[i][j] += av[i] * bv[j];
        }

        int cbase = pass * 64 + tx * 4;
        float b0 = 0.f, b1 = 0.f, b2 = 0.f, b3 = 0.f;
        if (pass == 0) {
            b0 = bm[tx * 4 + 0]; b1 = bm[tx * 4 + 1];
            b2 = bm[tx * 4 + 2]; b3 = bm[tx * 4 + 3];
        }
#pragma unroll
        for (int i = 0; i < 4; ++i) {
            int node = n0 + ty * 4 + i;
            if (node < NNODES) {
                float4 v;
                v.x = acc[i][0] + b0; v.y = acc[i][1] + b1;
                v.z = acc[i][2] + b2; v.w = acc[i][3] + b3;
                *(float4*)&g_feat[node * 256 + cbase] = v;
            }
        }
    }

    // tail: el/er (4 cols) from folded vectors
    __syncthreads();
    float* vs = sm + 128 * 68;  // reuse ws region as flat [512]
    for (int idx = tid; idx < 512; idx += 256) vs[idx] = g_vlr[idx];
    __syncthreads();
    {
        int nn = tid >> 2, c = tid & 3;  // 64 nodes x 4 cols
        float s = 0.f;
#pragma unroll 8
        for (int k = 0; k < 128; ++k) s += xs[k][nn] * vs[k * 4 + c];
        int node = n0 + nn;
        if (node < NNODES) g_feat[node * 256 + 192 + c] = s;
    }
}

// ---------------- K2: per-node aggregation (mean, max, softmax attn, gate) -
__global__ void k2_aggregate(const float* __restrict__ x,
                             const int* __restrict__ src,
                             const float* __restrict__ Wg,
                             const float* __restrict__ bg) {
    const int n = blockIdx.x;
    const int t = threadIdx.x;  // 128
    __shared__ int ssrc[16];
    __shared__ float swh[16][128];
    __shared__ float se[2][16];
    __shared__ float salpha[2][16];
    __shared__ float red[128];

    if (t < 16) ssrc[t] = src[n * DEGC + t];
    __syncthreads();

    float mean = 0.f;
    float mz = -3.4e38f;
#pragma unroll
    for (int j = 0; j < 16; ++j) {
        int s = ssrc[j];
        mean += x[s * 128 + t];
        swh[j][t] = g_feat[s * 256 + 64 + t];
        if (t < 64) mz = fmaxf(mz, g_feat[s * 256 + t]);
    }
    mean *= (1.f / 16.f);

    if (t < 32) {
        int j = t >> 1, h = t & 1;
        float e = g_feat[ssrc[j] * 256 + 192 + h] + g_feat[n * 256 + 194 + h];
        se[h][j] = (e > 0.f) ? e : 0.2f * e;  // leaky_relu 0.2
    }
    __syncthreads();

    if (t < 2) {
        float m = -3.4e38f;
#pragma unroll
        for (int j = 0; j < 16; ++j) m = fmaxf(m, se[t][j]);
        float ssum = 0.f;
#pragma unroll
        for (int j = 0; j < 16; ++j) {
            float v = __expf(se[t][j] - m);
            salpha[t][j] = v;
            ssum += v;
        }
        float inv = 1.f / fmaxf(ssum, 1e-12f);
#pragma unroll
        for (int j = 0; j < 16; ++j) salpha[t][j] *= inv;
    }
    __syncthreads();

    const int h = t >> 6;
    float ao = 0.f;
#pragma unroll
    for (int j = 0; j < 16; ++j) ao += salpha[h][j] * swh[j][t];

    // gate = sigmoid([x, mean, max_z] @ Wg + bg), Wg is [320][2] row-major
    float xv = x[n * 128 + t];
    float p0 = xv * Wg[t * 2 + 0] + mean * Wg[(128 + t) * 2 + 0];
    float p1 = xv * Wg[t * 2 + 1] + mean * Wg[(128 + t) * 2 + 1];
    if (t < 64) {
        p0 += mz * Wg[(256 + t) * 2 + 0];
        p1 += mz * Wg[(256 + t) * 2 + 1];
    }
    red[t] = p0; __syncthreads();
    for (int o = 64; o > 0; o >>= 1) { if (t < o) red[t] += red[t + o]; __syncthreads(); }
    float gsum0 = red[0]; __syncthreads();
    red[t] = p1; __syncthreads();
    for (int o = 64; o > 0; o >>= 1) { if (t < o) red[t] += red[t + o]; __syncthreads(); }
    float gsum1 = red[0];

    float gate = sigmoidf_(((h == 0) ? gsum0 : gsum1) + bg[h]);
    g_gated[n * 128 + t] = gate * ao;
}

// ---------------- K3a: meso = [x | gated] @ Wmerge + bmerge ---------------
__global__ void k3a_merge(const float* __restrict__ x,
                          const float* __restrict__ Wmerge,
                          const float* __restrict__ bmerge) {
    extern __shared__ float sm[];
    float(*xs)[68] = (float(*)[68])sm;
    float(*ws)[68] = (float(*)[68])(sm + 128 * 68);
    const int tid = threadIdx.x;
    const int tx = tid & 15, ty = tid >> 4;
    const int n0 = blockIdx.x * 64;

    float acc[4][4] = {};
    for (int chunk = 0; chunk < 2; ++chunk) {
        __syncthreads();
        for (int idx = tid; idx < 64 * 128; idx += 256) {
            int nn = idx >> 7, k = idx & 127;
            int node = n0 + nn;
            float v = 0.f;
            if (node < NNODES)
                v = chunk ? g_gated[node * 128 + k] : x[node * 128 + k];
            xs[k][nn] = v;
        }
        for (int idx = tid; idx < 128 * 64; idx += 256) {
            int k = idx >> 6, c = idx & 63;
            ws[k][c] = Wmerge[(chunk * 128 + k) * 64 + c];
        }
        __syncthreads();
#pragma unroll 4
        for (int k = 0; k < 128; ++k) {
            float4 a4 = *(const float4*)&xs[k][ty * 4];
            float4 b4 = *(const float4*)&ws[k][tx * 4];
            float av[4] = {a4.x, a4.y, a4.z, a4.w};
            float bv[4] = {b4.x, b4.y, b4.z, b4.w};
#pragma unroll
            for (int i = 0; i < 4; ++i)
#pragma unroll
                for (int j = 0; j < 4; ++j) acc[i][j] += av[i] * bv[j];
        }
    }
#pragma unroll
    for (int i = 0; i < 4; ++i) {
        int node = n0 + ty * 4 + i;
        if (node < NNODES) {
            float4 v;
            v.x = acc[i][0] + bmerge[tx * 4 + 0];
            v.y = acc[i][1] + bmerge[tx * 4 + 1];
            v.z = acc[i][2] + bmerge[tx * 4 + 2];
            v.w = acc[i][3] + bmerge[tx * 4 + 3];
            *(float4*)&g_meso[node * 64 + tx * 4] = v;
        }
    }
}

// ---------------- K3b: GRU cell + output projection ------------------------
__global__ void k3b_gru_out(const float* __restrict__ hin,
                            const float* __restrict__ W_ih,
                            const float* __restrict__ W_hh,
                            const float* __restrict__ b_ih,
                            const float* __restrict__ b_hh,
                            const float* __restrict__ Wout,
                            const float* __restrict__ bout,
                            float* __restrict__ out) {
    extern __shared__ float sm[];
    float(*ms)[68] = (float(*)[68])sm;                   // meso, k-major [64][68]
    float(*hs)[68] = (float(*)[68])(sm + 64 * 68);       // hidden, k-major
    float(*wi)[68] = (float(*)[68])(sm + 2 * 64 * 68);   // W_ih tile (transposed)
    float(*wh)[68] = (float(*)[68])(sm + 3 * 64 * 68);   // W_hh tile (transposed)
    float(*nh)[68] = (float(*)[68])(sm + 4 * 64 * 68);   // new hidden, node-major
    const int tid = threadIdx.x;
    const int tx = tid & 15, ty = tid >> 4;
    const int n0 = blockIdx.x * 64;

    for (int idx = tid; idx < 64 * 64; idx += 256) {
        int nn = idx >> 6, k = idx & 63;
        int node = n0 + nn;
        ms[k][nn] = (node < NNODES) ? g_meso[node * 64 + k] : 0.f;
        hs[k][nn] = (node < NNODES) ? hin[node * 64 + k] : 0.f;
    }

    float rr[4][4], zz[4][4];
    for (int g = 0; g < 3; ++g) {
        __syncthreads();
        for (int idx = tid; idx < 64 * 64; idx += 256) {
            int c = idx >> 6, k = idx & 63;  // note: global reads coalesced over k
            wi[k][c] = W_ih[(g * 64 + c) * 64 + k];
            wh[k][c] = W_hh[(g * 64 + c) * 64 + k];
        }
        __syncthreads();

        float ai[4][4] = {}, ah[4][4] = {};
#pragma unroll 4
        for (int k = 0; k < 64; ++k) {
            float4 a4 = *(const float4*)&ms[k][ty * 4];
            float4 h4 = *(const float4*)&hs[k][ty * 4];
            float4 bi4 = *(const float4*)&wi[k][tx * 4];
            float4 bh4 = *(const float4*)&wh[k][tx * 4];
            float av[4] = {a4.x, a4.y, a4.z, a4.w};
            float hv[4] = {h4.x, h4.y, h4.z, h4.w};
            float biv[4] = {bi4.x, bi4.y, bi4.z, bi4.w};
            float bhv[4] = {bh4.x, bh4.y, bh4.z, bh4.w};
#pragma unroll
            for (int i = 0; i < 4; ++i)
#pragma unroll
                for (int j = 0; j < 4; ++j) {
                    ai[i][j] += av[i] * biv[j];
                    ah[i][j] += hv[i] * bhv[j];
                }
        }

        if (g == 0) {
#pragma unroll
            for (int i = 0; i < 4; ++i)
#pragma unroll
                for (int j = 0; j < 4; ++j) {
                    float gi = ai[i][j] + b_ih[g * 64 + tx * 4 + j];
                    float gh = ah[i][j] + b_hh[g * 64 + tx * 4 + j];
                    rr[i][j] = sigmoidf_(gi + gh);
                }
        } else if (g == 1) {
#pragma unroll
            for (int i = 0; i < 4; ++i)
#pragma unroll
                for (int j = 0; j < 4; ++j) {
                    float gi = ai[i][j] + b_ih[g * 64 + tx * 4 + j];
                    float gh = ah[i][j] + b_hh[g * 64 + tx * 4 + j];
                    zz[i][j] = sigmoidf_(gi + gh);
                }
        } else {
#pragma unroll
            for (int i = 0; i < 4; ++i) {
                float v[4];
#pragma unroll
                for (int j = 0; j < 4; ++j) {
                    float gi = ai[i][j] + b_ih[g * 64 + tx * 4 + j];
                    float gh = ah[i][j] + b_hh[g * 64 + tx * 4 + j];
                    float ng = tanhf(gi + rr[i][j] * gh);
                    float hval = hs[tx * 4 + j][ty * 4 + i];
                    v[j] = (1.f - zz[i][j]) * ng + zz[i][j] * hval;
                }
                float4 v4 = make_float4(v[0], v[1], v[2], v[3]);
                *(float4*)&nh[ty * 4 + i][tx * 4] = v4;
                int node = n0 + ty * 4 + i;
                if (node < NNODES)
                    *(float4*)&out[(size_t)NNODES * 64 + node * 64 + tx * 4] = v4;
            }
        }
    }

    __syncthreads();
    // output projection: source = nh @ Wout + bout (reuse wi for Wout)
    for (int idx = tid; idx < 64 * 64; idx += 256) {
        int k = idx >> 6, c = idx & 63;
        wi[k][c] = Wout[k * 64 + c];
    }
    __syncthreads();

    float acc[4][4] = {};
#pragma unroll 4
    for (int k = 0; k < 64; ++k) {
        float4 b4 = *(const float4*)&wi[k][tx * 4];
        float bv[4] = {b4.x, b4.y, b4.z, b4.w};
        float av[4];
#pragma unroll
        for (int i = 0; i < 4; ++i) av[i] = nh[ty * 4 + i][k];
#pragma unroll
        for (int i = 0; i < 4; ++i)
#pragma unroll
            for (int j = 0; j < 4; ++j) acc[i][j] += av[i] * bv[j];
    }
#pragma unroll
    for (int i = 0; i < 4; ++i) {
        int node = n0 + ty * 4 + i;
        if (node < NNODES) {
            float4 v;
            v.x = acc[i][0] + bout[tx * 4 + 0];
            v.y = acc[i][1] + bout[tx * 4 + 1];
            v.z = acc[i][2] + bout[tx * 4 + 2];
            v.w = acc[i][3] + bout[tx * 4 + 3];
            *(float4*)&out[node * 64 + tx * 4] = v;
        }
    }
}

// ---------------- launch ---------------------------------------------------
extern "C" void kernel_launch(void* const* d_in, const int* in_sizes, int n_in,
                              void* d_out, int out_size) {
    const float* x   = (const float*)d_in[0];
    const float* hin = (const float*)d_in[1];
    const int*   srcp = (const int*)d_in[2];
    // d_in[3] = dst (structurally repeat(arange(N),16); not needed)
    const float* Wm  = (const float*)d_in[4];
    const float* bm  = (const float*)d_in[5];
    const float* Wg  = (const float*)d_in[6];
    const float* bg  = (const float*)d_in[7];
    const float* Wfc = (const float*)d_in[8];
    const float* al  = (const float*)d_in[9];
    const float* ar  = (const float*)d_in[10];
    const float* Wmg = (const float*)d_in[11];
    const float* bmg = (const float*)d_in[12];
    const float* Wih = (const float*)d_in[13];
    const float* Whh = (const float*)d_in[14];
    const float* bih = (const float*)d_in[15];
    const float* bhh = (const float*)d_in[16];
    const float* Wo  = (const float*)d_in[17];
    const float* bo  = (const float*)d_in[18];
    float* out = (float*)d_out;

    cudaFuncSetAttribute(k1_node_linear, cudaFuncAttributeMaxDynamicSharedMemorySize, 69632);
    cudaFuncSetAttribute(k3a_merge, cudaFuncAttributeMaxDynamicSharedMemorySize, 69632);
    cudaFuncSetAttribute(k3b_gru_out, cudaFuncAttributeMaxDynamicSharedMemorySize, 87040);

    int nb = (NNODES + 63) / 64;
    k0_fold_attn<<<1, 128>>>(Wfc, al, ar);
    k1_node_linear<<<nb, 256, 69632>>>(x, Wm, bm, Wfc);
    k2_aggregate<<<NNODES, 128>>>(x, srcp, Wg, bg);
    k3a_merge<<<nb, 256, 69632>>>(x, Wmg, bmg);
    k3b_gru_out<<<nb, 256, 87040>>>(hin, Wih, Whh, bih, bhh, Wo, bo, out);
}

// round 3
// speedup vs baseline: 1.0793x; 1.0793x over previous
#include <cuda_runtime.h>
#include <math.h>

#define NNODES 50000
#define DEGC 16

// ---------------- scratch (device globals; no runtime allocation) ----------
// g_feat per node (256 floats): [0..63]=z, [64..191]=Wh, [192..193]=el, [194..195]=er
__device__ float g_feat[NNODES * 256];
__device__ float g_gated[NNODES * 128];
__device__ float g_meso[NNODES * 64];
__device__ float g_vlr[128 * 4];   // [k][el0,el1,er0,er1]

__device__ __forceinline__ float sigmoidf_(float v) { return 1.f / (1.f + __expf(-v)); }

__device__ __forceinline__ unsigned f2tf(float v) {
    unsigned r;
    asm("cvt.rna.tf32.f32 %0, %1;" : "=r"(r) : "f"(v));
    return r;
}

__device__ __forceinline__ void mma_tf32(float c[4], unsigned a0, unsigned a1,
                                         unsigned a2, unsigned a3,
                                         unsigned b0, unsigned b1) {
    asm volatile(
        "mma.sync.aligned.m16n8k8.row.col.f32.tf32.tf32.f32 "
        "{%0,%1,%2,%3}, {%4,%5,%6,%7}, {%8,%9}, {%0,%1,%2,%3};"
        : "+f"(c[0]), "+f"(c[1]), "+f"(c[2]), "+f"(c[3])
        : "r"(a0), "r"(a1), "r"(a2), "r"(a3), "r"(b0), "r"(b1));
}

// ---------------- K0: fold attn_l / attn_r into per-k vectors --------------
__global__ void k0_fold_attn(const float* __restrict__ Wfc,
                             const float* __restrict__ al,
                             const float* __restrict__ ar) {
    int k = threadIdx.x;  // 128 threads
#pragma unroll
    for (int h = 0; h < 2; ++h) {
        float sl = 0.f, sr = 0.f;
#pragma unroll 8
        for (int q = 0; q < 64; ++q) {
            float w = Wfc[k * 128 + h * 64 + q];
            sl += w * al[h * 64 + q];
            sr += w * ar[h * 64 + q];
        }
        g_vlr[k * 4 + h] = sl;
        g_vlr[k * 4 + 2 + h] = sr;
    }
}

// A tile: [64 nodes][140] (stride 140 words: 12r+k conflict-free)
// B tile: [128 k][72]     (stride 72 words: 8k+n conflict-free)
#define AS_STRIDE 140
#define BS_STRIDE 72
#define K1_SMEM ((64 * AS_STRIDE + 128 * BS_STRIDE) * 4)   // 72704 B

// ---------------- K1: z | Wh | el | er via tf32 mma ------------------------
__global__ __launch_bounds__(128) void k1_node_linear(
    const float* __restrict__ x, const float* __restrict__ Wm,
    const float* __restrict__ bm, const float* __restrict__ Wfc) {
    extern __shared__ float sm[];
    float(*As)[AS_STRIDE] = (float(*)[AS_STRIDE])sm;
    float(*Bs)[BS_STRIDE] = (float(*)[BS_STRIDE])(sm + 64 * AS_STRIDE);
    const int tid = threadIdx.x, lane = tid & 31, wid = tid >> 5;
    const int n0 = blockIdx.x * 64;
    const int row0 = wid * 16 + (lane >> 2);
    const int kq = lane & 3;
    const int cn = lane >> 2;

    for (int idx = tid; idx < 64 * 128; idx += 128) {
        int nn = idx >> 7, k = idx & 127;
        int node = n0 + nn;
        float v = (node < NNODES) ? x[node * 128 + k] : 0.f;
        As[nn][k] = __uint_as_float(f2tf(v));
    }

    for (int pass = 0; pass < 3; ++pass) {
        __syncthreads();
        for (int idx = tid; idx < 128 * 64; idx += 128) {
            int k = idx >> 6, c = idx & 63;
            float w = (pass == 0) ? Wm[k * 64 + c] : Wfc[k * 128 + (pass - 1) * 64 + c];
            Bs[k][c] = __uint_as_float(f2tf(w));
        }
        __syncthreads();

        float C[8][4];
#pragma unroll
        for (int nt = 0; nt < 8; ++nt)
#pragma unroll
            for (int e = 0; e < 4; ++e) C[nt][e] = 0.f;

#pragma unroll
        for (int ks = 0; ks < 16; ++ks) {
            int kb = ks * 8;
            unsigned a0 = __float_as_uint(As[row0][kb + kq]);
            unsigned a1 = __float_as_uint(As[row0 + 8][kb + kq]);
            unsigned a2 = __float_as_uint(As[row0][kb + kq + 4]);
            unsigned a3 = __float_as_uint(As[row0 + 8][kb + kq + 4]);
#pragma unroll
            for (int nt = 0; nt < 8; ++nt) {
                unsigned b0 = __float_as_uint(Bs[kb + kq][nt * 8 + cn]);
                unsigned b1 = __float_as_uint(Bs[kb + kq + 4][nt * 8 + cn]);
                mma_tf32(C[nt], a0, a1, a2, a3, b0, b1);
            }
        }

        int cb = pass * 64;
        int node0 = n0 + row0, node1 = node0 + 8;
#pragma unroll
        for (int nt = 0; nt < 8; ++nt) {
            int c0 = nt * 8 + (lane & 3) * 2;
            float ba = 0.f, bb = 0.f;
            if (pass == 0) { ba = bm[c0]; bb = bm[c0 + 1]; }
            if (node0 < NNODES)
                *(float2*)&g_feat[node0 * 256 + cb + c0] =
                    make_float2(C[nt][0] + ba, C[nt][1] + bb);
            if (node1 < NNODES)
                *(float2*)&g_feat[node1 * 256 + cb + c0] =
                    make_float2(C[nt][2] + ba, C[nt][3] + bb);
        }
    }

    // el/er tail
    __syncthreads();
    float* vs = (float*)Bs;
    for (int idx = tid; idx < 512; idx += 128) vs[idx] = g_vlr[idx];
    __syncthreads();
#pragma unroll
    for (int w = 0; w < 2; ++w) {
        int it = tid + w * 128;
        int nn = it >> 2, c = it & 3;
        float s = 0.f;
#pragma unroll 16
        for (int k = 0; k < 128; ++k) s += As[nn][k] * vs[k * 4 + c];
        int node = n0 + nn;
        if (node < NNODES) g_feat[node * 256 + 192 + c] = s;
    }
}

// ---------------- K2: per-node aggregation (unchanged, gather-bound) -------
__global__ void k2_aggregate(const float* __restrict__ x,
                             const int* __restrict__ src,
                             const float* __restrict__ Wg,
                             const float* __restrict__ bg) {
    const int n = blockIdx.x;
    const int t = threadIdx.x;  // 128
    __shared__ int ssrc[16];
    __shared__ float swh[16][128];
    __shared__ float se[2][16];
    __shared__ float salpha[2][16];
    __shared__ float red[128];

    if (t < 16) ssrc[t] = src[n * DEGC + t];
    __syncthreads();

    float mean = 0.f;
    float mz = -3.4e38f;
#pragma unroll
    for (int j = 0; j < 16; ++j) {
        int s = ssrc[j];
        mean += x[s * 128 + t];
        swh[j][t] = g_feat[s * 256 + 64 + t];
        if (t < 64) mz = fmaxf(mz, g_feat[s * 256 + t]);
    }
    mean *= (1.f / 16.f);

    if (t < 32) {
        int j = t >> 1, h = t & 1;
        float e = g_feat[ssrc[j] * 256 + 192 + h] + g_feat[n * 256 + 194 + h];
        se[h][j] = (e > 0.f) ? e : 0.2f * e;
    }
    __syncthreads();

    if (t < 2) {
        float m = -3.4e38f;
#pragma unroll
        for (int j = 0; j < 16; ++j) m = fmaxf(m, se[t][j]);
        float ssum = 0.f;
#pragma unroll
        for (int j = 0; j < 16; ++j) {
            float v = __expf(se[t][j] - m);
            salpha[t][j] = v;
            ssum += v;
        }
        float inv = 1.f / fmaxf(ssum, 1e-12f);
#pragma unroll
        for (int j = 0; j < 16; ++j) salpha[t][j] *= inv;
    }
    __syncthreads();

    const int h = t >> 6;
    float ao = 0.f;
#pragma unroll
    for (int j = 0; j < 16; ++j) ao += salpha[h][j] * swh[j][t];

    float xv = x[n * 128 + t];
    float p0 = xv * Wg[t * 2 + 0] + mean * Wg[(128 + t) * 2 + 0];
    float p1 = xv * Wg[t * 2 + 1] + mean * Wg[(128 + t) * 2 + 1];
    if (t < 64) {
        p0 += mz * Wg[(256 + t) * 2 + 0];
        p1 += mz * Wg[(256 + t) * 2 + 1];
    }
    red[t] = p0; __syncthreads();
    for (int o = 64; o > 0; o >>= 1) { if (t < o) red[t] += red[t + o]; __syncthreads(); }
    float gsum0 = red[0]; __syncthreads();
    red[t] = p1; __syncthreads();
    for (int o = 64; o > 0; o >>= 1) { if (t < o) red[t] += red[t + o]; __syncthreads(); }
    float gsum1 = red[0];

    float gate = sigmoidf_(((h == 0) ? gsum0 : gsum1) + bg[h]);
    g_gated[n * 128 + t] = gate * ao;
}

// ---------------- K3a: meso = [x | gated] @ Wmerge + bmerge (tf32) ---------
__global__ __launch_bounds__(128) void k3a_merge(
    const float* __restrict__ x, const float* __restrict__ Wmerge,
    const float* __restrict__ bmerge) {
    extern __shared__ float sm[];
    float(*As)[AS_STRIDE] = (float(*)[AS_STRIDE])sm;
    float(*Bs)[BS_STRIDE] = (float(*)[BS_STRIDE])(sm + 64 * AS_STRIDE);
    const int tid = threadIdx.x, lane = tid & 31, wid = tid >> 5;
    const int n0 = blockIdx.x * 64;
    const int row0 = wid * 16 + (lane >> 2);
    const int kq = lane & 3;
    const int cn = lane >> 2;

    float C[8][4];
#pragma unroll
    for (int nt = 0; nt < 8; ++nt)
#pragma unroll
        for (int e = 0; e < 4; ++e) C[nt][e] = 0.f;

    for (int chunk = 0; chunk < 2; ++chunk) {
        __syncthreads();
        for (int idx = tid; idx < 64 * 128; idx += 128) {
            int nn = idx >> 7, k = idx & 127;
            int node = n0 + nn;
            float v = 0.f;
            if (node < NNODES)
                v = chunk ? g_gated[node * 128 + k] : x[node * 128 + k];
            As[nn][k] = __uint_as_float(f2tf(v));
        }
        for (int idx = tid; idx < 128 * 64; idx += 128) {
            int k = idx >> 6, c = idx & 63;
            Bs[k][c] = __uint_as_float(f2tf(Wmerge[(chunk * 128 + k) * 64 + c]));
        }
        __syncthreads();
#pragma unroll
        for (int ks = 0; ks < 16; ++ks) {
            int kb = ks * 8;
            unsigned a0 = __float_as_uint(As[row0][kb + kq]);
            unsigned a1 = __float_as_uint(As[row0 + 8][kb + kq]);
            unsigned a2 = __float_as_uint(As[row0][kb + kq + 4]);
            unsigned a3 = __float_as_uint(As[row0 + 8][kb + kq + 4]);
#pragma unroll
            for (int nt = 0; nt < 8; ++nt) {
                unsigned b0 = __float_as_uint(Bs[kb + kq][nt * 8 + cn]);
                unsigned b1 = __float_as_uint(Bs[kb + kq + 4][nt * 8 + cn]);
                mma_tf32(C[nt], a0, a1, a2, a3, b0, b1);
            }
        }
    }
    int node0 = n0 + row0, node1 = node0 + 8;
#pragma unroll
    for (int nt = 0; nt < 8; ++nt) {
        int c0 = nt * 8 + (lane & 3) * 2;
        float ba = bmerge[c0], bb = bmerge[c0 + 1];
        if (node0 < NNODES)
            *(float2*)&g_meso[node0 * 64 + c0] = make_float2(C[nt][0] + ba, C[nt][1] + bb);
        if (node1 < NNODES)
            *(float2*)&g_meso[node1 * 64 + c0] = make_float2(C[nt][2] + ba, C[nt][3] + bb);
    }
}

// ---------------- K3b: GRU cell + output projection (tf32 mma) -------------
#define MS_STRIDE 76   // 12r+k conflict-free for K=64
#define WT_STRIDE 72
#define K3B_SMEM ((64 * MS_STRIDE * 3 + 64 * WT_STRIDE * 2) * 4)  // 95232 B

__global__ __launch_bounds__(128) void k3b_gru_out(
    const float* __restrict__ hin, const float* __restrict__ W_ih,
    const float* __restrict__ W_hh, const float* __restrict__ b_ih,
    const float* __restrict__ b_hh, const float* __restrict__ Wout,
    const float* __restrict__ bout, float* __restrict__ out) {
    extern __shared__ float sm[];
    float(*ms)[MS_STRIDE] = (float(*)[MS_STRIDE])sm;
    float(*hs)[MS_STRIDE] = (float(*)[MS_STRIDE])(sm + 64 * MS_STRIDE);
    float(*nh)[MS_STRIDE] = (float(*)[MS_STRIDE])(sm + 2 * 64 * MS_STRIDE);
    float(*wi)[WT_STRIDE] = (float(*)[WT_STRIDE])(sm + 3 * 64 * MS_STRIDE);
    float(*wh)[WT_STRIDE] = (float(*)[WT_STRIDE])(sm + 3 * 64 * MS_STRIDE + 64 * WT_STRIDE);
    const int tid = threadIdx.x, lane = tid & 31, wid = tid >> 5;
    const int n0 = blockIdx.x * 64;
    const int row0 = wid * 16 + (lane >> 2);
    const int kq = lane & 3;
    const int cn = lane >> 2;

    for (int idx = tid; idx < 64 * 64; idx += 128) {
        int nn = idx >> 6, k = idx & 63;
        int node = n0 + nn;
        float mv = (node < NNODES) ? g_meso[node * 64 + k] : 0.f;
        float hv = (node < NNODES) ? hin[node * 64 + k] : 0.f;
        ms[nn][k] = __uint_as_float(f2tf(mv));
        hs[nn][k] = hv;  // raw fp32: exact for elementwise, truncated by mma
    }

    float rr[8][4], zz[8][4];
    const int node0 = n0 + row0, node1 = node0 + 8;

    for (int g = 0; g < 3; ++g) {
        __syncthreads();
        for (int idx = tid; idx < 64 * 64; idx += 128) {
            int c = idx >> 6, k = idx & 63;
            wi[k][c] = __uint_as_float(f2tf(W_ih[(g * 64 + c) * 64 + k]));
            wh[k][c] = __uint_as_float(f2tf(W_hh[(g * 64 + c) * 64 + k]));
        }
        __syncthreads();

        float ai[8][4], ah[8][4];
#pragma unroll
        for (int nt = 0; nt < 8; ++nt)
#pragma unroll
            for (int e = 0; e < 4; ++e) { ai[nt][e] = 0.f; ah[nt][e] = 0.f; }

#pragma unroll
        for (int ks = 0; ks < 8; ++ks) {
            int kb = ks * 8;
            unsigned a0 = __float_as_uint(ms[row0][kb + kq]);
            unsigned a1 = __float_as_uint(ms[row0 + 8][kb + kq]);
            unsigned a2 = __float_as_uint(ms[row0][kb + kq + 4]);
            unsigned a3 = __float_as_uint(ms[row0 + 8][kb + kq + 4]);
            unsigned h0 = __float_as_uint(hs[row0][kb + kq]);
            unsigned h1 = __float_as_uint(hs[row0 + 8][kb + kq]);
            unsigned h2 = __float_as_uint(hs[row0][kb + kq + 4]);
            unsigned h3 = __float_as_uint(hs[row0 + 8][kb + kq + 4]);
#pragma unroll
            for (int nt = 0; nt < 8; ++nt) {
                unsigned bi0 = __float_as_uint(wi[kb + kq][nt * 8 + cn]);
                unsigned bi1 = __float_as_uint(wi[kb + kq + 4][nt * 8 + cn]);
                unsigned bh0 = __float_as_uint(wh[kb + kq][nt * 8 + cn]);
                unsigned bh1 = __float_as_uint(wh[kb + kq + 4][nt * 8 + cn]);
                mma_tf32(ai[nt], a0, a1, a2, a3, bi0, bi1);
                mma_tf32(ah[nt], h0, h1, h2, h3, bh0, bh1);
            }
        }

#pragma unroll
        for (int nt = 0; nt < 8; ++nt) {
#pragma unroll
            for (int e = 0; e < 4; ++e) {
                int c = nt * 8 + (lane & 3) * 2 + (e & 1);
                int r = row0 + (e >> 1) * 8;
                float gi = ai[nt][e] + b_ih[g * 64 + c];
                float gh = ah[nt][e] + b_hh[g * 64 + c];
                if (g == 0) {
                    rr[nt][e] = sigmoidf_(gi + gh);
                } else if (g == 1) {
                    zz[nt][e] = sigmoidf_(gi + gh);
                } else {
                    float ng = tanhf(gi + rr[nt][e] * gh);
                    float hv = hs[r][c];
                    float v = (1.f - zz[nt][e]) * ng + zz[nt][e] * hv;
                    int node = n0 + r;
                    if (node < NNODES)
                        out[(size_t)NNODES * 64 + (size_t)node * 64 + c] = v;
                    nh[r][c] = __uint_as_float(f2tf(v));
                }
            }
        }
    }

    __syncthreads();
    for (int idx = tid; idx < 64 * 64; idx += 128) {
        int k = idx >> 6, c = idx & 63;
        wi[k][c] = __uint_as_float(f2tf(Wout[k * 64 + c]));
    }
    __syncthreads();

    float C[8][4];
#pragma unroll
    for (int nt = 0; nt < 8; ++nt)
#pragma unroll
        for (int e = 0; e < 4; ++e) C[nt][e] = 0.f;
#pragma unroll
    for (int ks = 0; ks < 8; ++ks) {
        int kb = ks * 8;
        unsigned a0 = __float_as_uint(nh[row0][kb + kq]);
        unsigned a1 = __float_as_uint(nh[row0 + 8][kb + kq]);
        unsigned a2 = __float_as_uint(nh[row0][kb + kq + 4]);
        unsigned a3 = __float_as_uint(nh[row0 + 8][kb + kq + 4]);
#pragma unroll
        for (int nt = 0; nt < 8; ++nt) {
            unsigned b0 = __float_as_uint(wi[kb + kq][nt * 8 + cn]);
            unsigned b1 = __float_as_uint(wi[kb + kq + 4][nt * 8 + cn]);
            mma_tf32(C[nt], a0, a1, a2, a3, b0, b1);
        }
    }
#pragma unroll
    for (int nt = 0; nt < 8; ++nt) {
        int c0 = nt * 8 + (lane & 3) * 2;
        float ba = bout[c0], bb = bout[c0 + 1];
        if (node0 < NNODES)
            *(float2*)&out[(size_t)node0 * 64 + c0] = make_float2(C[nt][0] + ba, C[nt][1] + bb);
        if (node1 < NNODES)
            *(float2*)&out[(size_t)node1 * 64 + c0] = make_float2(C[nt][2] + ba, C[nt][3] + bb);
    }
}

// ---------------- launch ---------------------------------------------------
extern "C" void kernel_launch(void* const* d_in, const int* in_sizes, int n_in,
                              void* d_out, int out_size) {
    const float* x    = (const float*)d_in[0];
    const float* hin  = (const float*)d_in[1];
    const int*   srcp = (const int*)d_in[2];
    const float* Wm   = (const float*)d_in[4];
    const float* bm   = (const float*)d_in[5];
    const float* Wg   = (const float*)d_in[6];
    const float* bg   = (const float*)d_in[7];
    const float* Wfc  = (const float*)d_in[8];
    const float* al   = (const float*)d_in[9];
    const float* ar   = (const float*)d_in[10];
    const float* Wmg  = (const float*)d_in[11];
    const float* bmg  = (const float*)d_in[12];
    const float* Wih  = (const float*)d_in[13];
    const float* Whh  = (const float*)d_in[14];
    const float* bih  = (const float*)d_in[15];
    const float* bhh  = (const float*)d_in[16];
    const float* Wo   = (const float*)d_in[17];
    const float* bo   = (const float*)d_in[18];
    float* out = (float*)d_out;

    cudaFuncSetAttribute(k1_node_linear, cudaFuncAttributeMaxDynamicSharedMemorySize, K1_SMEM);
    cudaFuncSetAttribute(k3a_merge, cudaFuncAttributeMaxDynamicSharedMemorySize, K1_SMEM);
    cudaFuncSetAttribute(k3b_gru_out, cudaFuncAttributeMaxDynamicSharedMemorySize, K3B_SMEM);

    int nb = (NNODES + 63) / 64;
    k0_fold_attn<<<1, 128>>>(Wfc, al, ar);
    k1_node_linear<<<nb, 128, K1_SMEM>>>(x, Wm, bm, Wfc);
    k2_aggregate<<<NNODES, 128>>>(x, srcp, Wg, bg);
    k3a_merge<<<nb, 128, K1_SMEM>>>(x, Wmg, bmg);
    k3b_gru_out<<<nb, 128, K3B_SMEM>>>(hin, Wih, Whh, bih, bhh, Wo, bo, out);
}

// round 4
// speedup vs baseline: 1.2528x; 1.1607x over previous
#include <cuda_runtime.h>
#include <math.h>

#define NNODES 50000
#define DEGC 16

// ---------------- scratch (device globals) ---------------------------------
__device__ float g_z[NNODES * 64];      // z = x@Wm+bm
__device__ float g_e[NNODES * 4];       // el0, el1, er0, er1
__device__ float g_xw[NNODES * 256];    // per-head alpha-weighted x sums [h][128]
__device__ float g_gate[NNODES * 2];    // gate per head
__device__ float g_gated[NNODES * 128]; // gate * attn_out
__device__ float g_meso[NNODES * 64];
__device__ float g_vlr[128 * 4];        // [k][el0,el1,er0,er1]

__device__ __forceinline__ float sigmoidf_(float v) { return 1.f / (1.f + __expf(-v)); }

__device__ __forceinline__ unsigned f2tf(float v) {
    unsigned r;
    asm("cvt.rna.tf32.f32 %0, %1;" : "=r"(r) : "f"(v));
    return r;
}

__device__ __forceinline__ void mma_tf32(float c[4], unsigned a0, unsigned a1,
                                         unsigned a2, unsigned a3,
                                         unsigned b0, unsigned b1) {
    asm volatile(
        "mma.sync.aligned.m16n8k8.row.col.f32.tf32.tf32.f32 "
        "{%0,%1,%2,%3}, {%4,%5,%6,%7}, {%8,%9}, {%0,%1,%2,%3};"
        : "+f"(c[0]), "+f"(c[1]), "+f"(c[2]), "+f"(c[3])
        : "r"(a0), "r"(a1), "r"(a2), "r"(a3), "r"(b0), "r"(b1));
}

#define AS_STRIDE 140   // 64 rows x K=128, 12r+k conflict-free
#define BS_STRIDE 72    // 128 k x 64 cols, 8k+n conflict-free
#define K1_SMEM ((64 * AS_STRIDE + 128 * BS_STRIDE) * 4)   // 72704 B
#define MS_STRIDE 76
#define WT_STRIDE 72
#define K3B_SMEM ((64 * MS_STRIDE * 3 + 64 * WT_STRIDE * 2) * 4)  // 95232 B

// ---------------- K0: fold attn vectors ------------------------------------
__global__ void k0_fold_attn(const float* __restrict__ Wfc,
                             const float* __restrict__ al,
                             const float* __restrict__ ar) {
    int k = threadIdx.x;  // 128
#pragma unroll
    for (int h = 0; h < 2; ++h) {
        float sl = 0.f, sr = 0.f;
#pragma unroll 8
        for (int q = 0; q < 64; ++q) {
            float w = Wfc[k * 128 + h * 64 + q];
            sl += w * al[h * 64 + q];
            sr += w * ar[h * 64 + q];
        }
        g_vlr[k * 4 + h] = sl;
        g_vlr[k * 4 + 2 + h] = sr;
    }
}

// ---------------- K1: z = x@Wm+bm ; el/er tail (8 warps) -------------------
__global__ __launch_bounds__(256) void k1_node_linear(
    const float* __restrict__ x, const float* __restrict__ Wm,
    const float* __restrict__ bm) {
    extern __shared__ float sm[];
    float(*As)[AS_STRIDE] = (float(*)[AS_STRIDE])sm;
    float(*Bs)[BS_STRIDE] = (float(*)[BS_STRIDE])(sm + 64 * AS_STRIDE);
    const int tid = threadIdx.x, lane = tid & 31, wid = tid >> 5;
    const int n0 = blockIdx.x * 64;
    const int row0 = (wid >> 1) * 16 + (lane >> 2);
    const int colh = (wid & 1) * 32;
    const int kq = lane & 3;
    const int cn = lane >> 2;

    for (int idx = tid; idx < 64 * 128; idx += 256) {
        int nn = idx >> 7, k = idx & 127;
        int node = n0 + nn;
        float v = (node < NNODES) ? x[node * 128 + k] : 0.f;
        As[nn][k] = __uint_as_float(f2tf(v));
    }
    for (int idx = tid; idx < 128 * 64; idx += 256) {
        int k = idx >> 6, c = idx & 63;
        Bs[k][c] = __uint_as_float(f2tf(Wm[k * 64 + c]));
    }
    __syncthreads();

    float C[4][4];
#pragma unroll
    for (int nt = 0; nt < 4; ++nt)
#pragma unroll
        for (int e = 0; e < 4; ++e) C[nt][e] = 0.f;

#pragma unroll
    for (int ks = 0; ks < 16; ++ks) {
        int kb = ks * 8;
        unsigned a0 = __float_as_uint(As[row0][kb + kq]);
        unsigned a1 = __float_as_uint(As[row0 + 8][kb + kq]);
        unsigned a2 = __float_as_uint(As[row0][kb + kq + 4]);
        unsigned a3 = __float_as_uint(As[row0 + 8][kb + kq + 4]);
#pragma unroll
        for (int nt = 0; nt < 4; ++nt) {
            int col = colh + nt * 8 + cn;
            unsigned b0 = __float_as_uint(Bs[kb + kq][col]);
            unsigned b1 = __float_as_uint(Bs[kb + kq + 4][col]);
            mma_tf32(C[nt], a0, a1, a2, a3, b0, b1);
        }
    }

    int node0 = n0 + row0, node1 = node0 + 8;
#pragma unroll
    for (int nt = 0; nt < 4; ++nt) {
        int c0 = colh + nt * 8 + (lane & 3) * 2;
        float ba = bm[c0], bb = bm[c0 + 1];
        if (node0 < NNODES)
            *(float2*)&g_z[node0 * 64 + c0] = make_float2(C[nt][0] + ba, C[nt][1] + bb);
        if (node1 < NNODES)
            *(float2*)&g_z[node1 * 64 + c0] = make_float2(C[nt][2] + ba, C[nt][3] + bb);
    }

    // el/er tail: 64 nodes x 4 = 256 -> one per thread
    __syncthreads();
    float* vs = (float*)Bs;
    for (int idx = tid; idx < 512; idx += 256) vs[idx] = g_vlr[idx];
    __syncthreads();
    {
        int nn = tid >> 2, c = tid & 3;
        float s = 0.f;
#pragma unroll 16
        for (int k = 0; k < 128; ++k) s += As[nn][k] * vs[k * 4 + c];
        int node = n0 + nn;
        if (node < NNODES) g_e[node * 4 + c] = s;
    }
}

// ---------------- K2: gather + softmax + weighted-x + gate -----------------
__global__ void k2_aggregate(const float* __restrict__ x,
                             const int* __restrict__ src,
                             const float* __restrict__ Wg,
                             const float* __restrict__ bg) {
    const int n = blockIdx.x;
    const int t = threadIdx.x;  // 128
    __shared__ int ssrc[16];
    __shared__ float se[2][16];
    __shared__ float salpha[2][16];
    __shared__ float red[128];

    if (t < 16) ssrc[t] = src[n * DEGC + t];
    __syncthreads();

    float val[16];
    float mean = 0.f;
#pragma unroll
    for (int j = 0; j < 16; ++j) {
        val[j] = x[ssrc[j] * 128 + t];
        mean += val[j];
    }
    mean *= (1.f / 16.f);

    float mz = -3.4e38f;
    if (t < 64) {
#pragma unroll
        for (int j = 0; j < 16; ++j) mz = fmaxf(mz, g_z[ssrc[j] * 64 + t]);
    }

    if (t < 32) {
        int j = t >> 1, h = t & 1;
        float e = g_e[ssrc[j] * 4 + h] + g_e[n * 4 + 2 + h];
        se[h][j] = (e > 0.f) ? e : 0.2f * e;
    }
    __syncthreads();

    if (t < 2) {
        float m = -3.4e38f;
#pragma unroll
        for (int j = 0; j < 16; ++j) m = fmaxf(m, se[t][j]);
        float ssum = 0.f;
#pragma unroll
        for (int j = 0; j < 16; ++j) {
            float v = __expf(se[t][j] - m);
            salpha[t][j] = v;
            ssum += v;
        }
        float inv = 1.f / fmaxf(ssum, 1e-12f);
#pragma unroll
        for (int j = 0; j < 16; ++j) salpha[t][j] *= inv;
    }
    __syncthreads();

    float xw0 = 0.f, xw1 = 0.f;
#pragma unroll
    for (int j = 0; j < 16; ++j) {
        xw0 += salpha[0][j] * val[j];
        xw1 += salpha[1][j] * val[j];
    }
    g_xw[n * 256 + t] = xw0;
    g_xw[n * 256 + 128 + t] = xw1;

    // gate = sigmoid([x, mean, max_z] @ Wg + bg)
    float xv = x[n * 128 + t];
    float p0 = xv * Wg[t * 2 + 0] + mean * Wg[(128 + t) * 2 + 0];
    float p1 = xv * Wg[t * 2 + 1] + mean * Wg[(128 + t) * 2 + 1];
    if (t < 64) {
        p0 += mz * Wg[(256 + t) * 2 + 0];
        p1 += mz * Wg[(256 + t) * 2 + 1];
    }
    red[t] = p0; __syncthreads();
    for (int o = 64; o > 0; o >>= 1) { if (t < o) red[t] += red[t + o]; __syncthreads(); }
    if (t == 0) g_gate[n * 2 + 0] = sigmoidf_(red[0] + bg[0]);
    __syncthreads();
    red[t] = p1; __syncthreads();
    for (int o = 64; o > 0; o >>= 1) { if (t < o) red[t] += red[t + o]; __syncthreads(); }
    if (t == 0) g_gate[n * 2 + 1] = sigmoidf_(red[0] + bg[1]);
}

// ---------------- K_attn: gated = gate_h * (xw_h @ Wfc_h) ------------------
__global__ __launch_bounds__(256) void k_attn(const float* __restrict__ Wfc) {
    extern __shared__ float sm[];
    float(*As)[AS_STRIDE] = (float(*)[AS_STRIDE])sm;
    float(*Bs)[BS_STRIDE] = (float(*)[BS_STRIDE])(sm + 64 * AS_STRIDE);
    const int tid = threadIdx.x, lane = tid & 31, wid = tid >> 5;
    const int n0 = blockIdx.x * 64;
    const int h = blockIdx.y;
    const int row0 = (wid >> 1) * 16 + (lane >> 2);
    const int colh = (wid & 1) * 32;
    const int kq = lane & 3;
    const int cn = lane >> 2;

    for (int idx = tid; idx < 64 * 128; idx += 256) {
        int nn = idx >> 7, k = idx & 127;
        int node = n0 + nn;
        float v = (node < NNODES) ? g_xw[node * 256 + h * 128 + k] : 0.f;
        As[nn][k] = __uint_as_float(f2tf(v));
    }
    for (int idx = tid; idx < 128 * 64; idx += 256) {
        int k = idx >> 6, c = idx & 63;
        Bs[k][c] = __uint_as_float(f2tf(Wfc[k * 128 + h * 64 + c]));
    }
    __syncthreads();

    float C[4][4];
#pragma unroll
    for (int nt = 0; nt < 4; ++nt)
#pragma unroll
        for (int e = 0; e < 4; ++e) C[nt][e] = 0.f;

#pragma unroll
    for (int ks = 0; ks < 16; ++ks) {
        int kb = ks * 8;
        unsigned a0 = __float_as_uint(As[row0][kb + kq]);
        unsigned a1 = __float_as_uint(As[row0 + 8][kb + kq]);
        unsigned a2 = __float_as_uint(As[row0][kb + kq + 4]);
        unsigned a3 = __float_as_uint(As[row0 + 8][kb + kq + 4]);
#pragma unroll
        for (int nt = 0; nt < 4; ++nt) {
            int col = colh + nt * 8 + cn;
            unsigned b0 = __float_as_uint(Bs[kb + kq][col]);
            unsigned b1 = __float_as_uint(Bs[kb + kq + 4][col]);
            mma_tf32(C[nt], a0, a1, a2, a3, b0, b1);
        }
    }

    int node0 = n0 + row0, node1 = node0 + 8;
    float gg0 = (node0 < NNODES) ? g_gate[node0 * 2 + h] : 0.f;
    float gg1 = (node1 < NNODES) ? g_gate[node1 * 2 + h] : 0.f;
#pragma unroll
    for (int nt = 0; nt < 4; ++nt) {
        int c0 = colh + nt * 8 + (lane & 3) * 2;
        if (node0 < NNODES)
            *(float2*)&g_gated[node0 * 128 + h * 64 + c0] =
                make_float2(gg0 * C[nt][0], gg0 * C[nt][1]);
        if (node1 < NNODES)
            *(float2*)&g_gated[node1 * 128 + h * 64 + c0] =
                make_float2(gg1 * C[nt][2], gg1 * C[nt][3]);
    }
}

// ---------------- K3a: meso = [x | gated] @ Wmerge + bmerge ----------------
__global__ __launch_bounds__(256) void k3a_merge(
    const float* __restrict__ x, const float* __restrict__ Wmerge,
    const float* __restrict__ bmerge) {
    extern __shared__ float sm[];
    float(*As)[AS_STRIDE] = (float(*)[AS_STRIDE])sm;
    float(*Bs)[BS_STRIDE] = (float(*)[BS_STRIDE])(sm + 64 * AS_STRIDE);
    const int tid = threadIdx.x, lane = tid & 31, wid = tid >> 5;
    const int n0 = blockIdx.x * 64;
    const int row0 = (wid >> 1) * 16 + (lane >> 2);
    const int colh = (wid & 1) * 32;
    const int kq = lane & 3;
    const int cn = lane >> 2;

    float C[4][4];
#pragma unroll
    for (int nt = 0; nt < 4; ++nt)
#pragma unroll
        for (int e = 0; e < 4; ++e) C[nt][e] = 0.f;

    for (int chunk = 0; chunk < 2; ++chunk) {
        __syncthreads();
        for (int idx = tid; idx < 64 * 128; idx += 256) {
            int nn = idx >> 7, k = idx & 127;
            int node = n0 + nn;
            float v = 0.f;
            if (node < NNODES)
                v = chunk ? g_gated[node * 128 + k] : x[node * 128 + k];
            As[nn][k] = __uint_as_float(f2tf(v));
        }
        for (int idx = tid; idx < 128 * 64; idx += 256) {
            int k = idx >> 6, c = idx & 63;
            Bs[k][c] = __uint_as_float(f2tf(Wmerge[(chunk * 128 + k) * 64 + c]));
        }
        __syncthreads();
#pragma unroll
        for (int ks = 0; ks < 16; ++ks) {
            int kb = ks * 8;
            unsigned a0 = __float_as_uint(As[row0][kb + kq]);
            unsigned a1 = __float_as_uint(As[row0 + 8][kb + kq]);
            unsigned a2 = __float_as_uint(As[row0][kb + kq + 4]);
            unsigned a3 = __float_as_uint(As[row0 + 8][kb + kq + 4]);
#pragma unroll
            for (int nt = 0; nt < 4; ++nt) {
                int col = colh + nt * 8 + cn;
                unsigned b0 = __float_as_uint(Bs[kb + kq][col]);
                unsigned b1 = __float_as_uint(Bs[kb + kq + 4][col]);
                mma_tf32(C[nt], a0, a1, a2, a3, b0, b1);
            }
        }
    }
    int node0 = n0 + row0, node1 = node0 + 8;
#pragma unroll
    for (int nt = 0; nt < 4; ++nt) {
        int c0 = colh + nt * 8 + (lane & 3) * 2;
        float ba = bmerge[c0], bb = bmerge[c0 + 1];
        if (node0 < NNODES)
            *(float2*)&g_meso[node0 * 64 + c0] = make_float2(C[nt][0] + ba, C[nt][1] + bb);
        if (node1 < NNODES)
            *(float2*)&g_meso[node1 * 64 + c0] = make_float2(C[nt][2] + ba, C[nt][3] + bb);
    }
}

// ---------------- K3b: GRU cell + output projection ------------------------
__global__ __launch_bounds__(256) void k3b_gru_out(
    const float* __restrict__ hin, const float* __restrict__ W_ih,
    const float* __restrict__ W_hh, const float* __restrict__ b_ih,
    const float* __restrict__ b_hh, const float* __restrict__ Wout,
    const float* __restrict__ bout, float* __restrict__ out) {
    extern __shared__ float sm[];
    float(*ms)[MS_STRIDE] = (float(*)[MS_STRIDE])sm;
    float(*hs)[MS_STRIDE] = (float(*)[MS_STRIDE])(sm + 64 * MS_STRIDE);
    float(*nh)[MS_STRIDE] = (float(*)[MS_STRIDE])(sm + 2 * 64 * MS_STRIDE);
    float(*wi)[WT_STRIDE] = (float(*)[WT_STRIDE])(sm + 3 * 64 * MS_STRIDE);
    float(*wh)[WT_STRIDE] = (float(*)[WT_STRIDE])(sm + 3 * 64 * MS_STRIDE + 64 * WT_STRIDE);
    const int tid = threadIdx.x, lane = tid & 31, wid = tid >> 5;
    const int n0 = blockIdx.x * 64;
    const int row0 = (wid >> 1) * 16 + (lane >> 2);
    const int colh = (wid & 1) * 32;
    const int kq = lane & 3;
    const int cn = lane >> 2;

    for (int idx = tid; idx < 64 * 64; idx += 256) {
        int nn = idx >> 6, k = idx & 63;
        int node = n0 + nn;
        float mv = (node < NNODES) ? g_meso[node * 64 + k] : 0.f;
        float hv = (node < NNODES) ? hin[node * 64 + k] : 0.f;
        ms[nn][k] = __uint_as_float(f2tf(mv));
        hs[nn][k] = hv;
    }

    float rr[4][4], zz[4][4];
    const int node0 = n0 + row0, node1 = node0 + 8;

    for (int g = 0; g < 3; ++g) {
        __syncthreads();
        for (int idx = tid; idx < 64 * 64; idx += 256) {
            int c = idx >> 6, k = idx & 63;
            wi[k][c] = __uint_as_float(f2tf(W_ih[(g * 64 + c) * 64 + k]));
            wh[k][c] = __uint_as_float(f2tf(W_hh[(g * 64 + c) * 64 + k]));
        }
        __syncthreads();

        float ai[4][4], ah[4][4];
#pragma unroll
        for (int nt = 0; nt < 4; ++nt)
#pragma unroll
            for (int e = 0; e < 4; ++e) { ai[nt][e] = 0.f; ah[nt][e] = 0.f; }

#pragma unroll
        for (int ks = 0; ks < 8; ++ks) {
            int kb = ks * 8;
            unsigned a0 = __float_as_uint(ms[row0][kb + kq]);
            unsigned a1 = __float_as_uint(ms[row0 + 8][kb + kq]);
            unsigned a2 = __float_as_uint(ms[row0][kb + kq + 4]);
            unsigned a3 = __float_as_uint(ms[row0 + 8][kb + kq + 4]);
            unsigned h0 = __float_as_uint(hs[row0][kb + kq]);
            unsigned h1 = __float_as_uint(hs[row0 + 8][kb + kq]);
            unsigned h2 = __float_as_uint(hs[row0][kb + kq + 4]);
            unsigned h3 = __float_as_uint(hs[row0 + 8][kb + kq + 4]);
#pragma unroll
            for (int nt = 0; nt < 4; ++nt) {
                int col = colh + nt * 8 + cn;
                unsigned bi0 = __float_as_uint(wi[kb + kq][col]);
                unsigned bi1 = __float_as_uint(wi[kb + kq + 4][col]);
                unsigned bh0 = __float_as_uint(wh[kb + kq][col]);
                unsigned bh1 = __float_as_uint(wh[kb + kq + 4][col]);
                mma_tf32(ai[nt], a0, a1, a2, a3, bi0, bi1);
                mma_tf32(ah[nt], h0, h1, h2, h3, bh0, bh1);
            }
        }

#pragma unroll
        for (int nt = 0; nt < 4; ++nt) {
#pragma unroll
            for (int e = 0; e < 4; ++e) {
                int c = colh + nt * 8 + (lane & 3) * 2 + (e & 1);
                int r = row0 + (e >> 1) * 8;
                float gi = ai[nt][e] + b_ih[g * 64 + c];
                float gh = ah[nt][e] + b_hh[g * 64 + c];
                if (g == 0) {
                    rr[nt][e] = sigmoidf_(gi + gh);
                } else if (g == 1) {
                    zz[nt][e] = sigmoidf_(gi + gh);
                } else {
                    float ng = tanhf(gi + rr[nt][e] * gh);
                    float hv = hs[r][c];
                    float v = (1.f - zz[nt][e]) * ng + zz[nt][e] * hv;
                    int node = n0 + r;
                    if (node < NNODES)
                        out[(size_t)NNODES * 64 + (size_t)node * 64 + c] = v;
                    nh[r][c] = __uint_as_float(f2tf(v));
                }
            }
        }
    }

    __syncthreads();
    for (int idx = tid; idx < 64 * 64; idx += 256) {
        int k = idx >> 6, c = idx & 63;
        wi[k][c] = __uint_as_float(f2tf(Wout[k * 64 + c]));
    }
    __syncthreads();

    float C[4][4];
#pragma unroll
    for (int nt = 0; nt < 4; ++nt)
#pragma unroll
        for (int e = 0; e < 4; ++e) C[nt][e] = 0.f;
#pragma unroll
    for (int ks = 0; ks < 8; ++ks) {
        int kb = ks * 8;
        unsigned a0 = __float_as_uint(nh[row0][kb + kq]);
        unsigned a1 = __float_as_uint(nh[row0 + 8][kb + kq]);
        unsigned a2 = __float_as_uint(nh[row0][kb + kq + 4]);
        unsigned a3 = __float_as_uint(nh[row0 + 8][kb + kq + 4]);
#pragma unroll
        for (int nt = 0; nt < 4; ++nt) {
            int col = colh + nt * 8 + cn;
            unsigned b0 = __float_as_uint(wi[kb + kq][col]);
            unsigned b1 = __float_as_uint(wi[kb + kq + 4][col]);
            mma_tf32(C[nt], a0, a1, a2, a3, b0, b1);
        }
    }
#pragma unroll
    for (int nt = 0; nt < 4; ++nt) {
        int c0 = colh + nt * 8 + (lane & 3) * 2;
        float ba = bout[c0], bb = bout[c0 + 1];
        if (node0 < NNODES)
            *(float2*)&out[(size_t)node0 * 64 + c0] = make_float2(C[nt][0] + ba, C[nt][1] + bb);
        if (node1 < NNODES)
            *(float2*)&out[(size_t)node1 * 64 + c0] = make_float2(C[nt][2] + ba, C[nt][3] + bb);
    }
}

// ---------------- launch ---------------------------------------------------
extern "C" void kernel_launch(void* const* d_in, const int* in_sizes, int n_in,
                              void* d_out, int out_size) {
    const float* x    = (const float*)d_in[0];
    const float* hin  = (const float*)d_in[1];
    const int*   srcp = (const int*)d_in[2];
    const float* Wm   = (const float*)d_in[4];
    const float* bm   = (const float*)d_in[5];
    const float* Wg   = (const float*)d_in[6];
    const float* bg   = (const float*)d_in[7];
    const float* Wfc  = (const float*)d_in[8];
    const float* al   = (const float*)d_in[9];
    const float* ar   = (const float*)d_in[10];
    const float* Wmg  = (const float*)d_in[11];
    const float* bmg  = (const float*)d_in[12];
    const float* Wih  = (const float*)d_in[13];
    const float* Whh  = (const float*)d_in[14];
    const float* bih  = (const float*)d_in[15];
    const float* bhh  = (const float*)d_in[16];
    const float* Wo   = (const float*)d_in[17];
    const float* bo   = (const float*)d_in[18];
    float* out = (float*)d_out;

    cudaFuncSetAttribute(k1_node_linear, cudaFuncAttributeMaxDynamicSharedMemorySize, K1_SMEM);
    cudaFuncSetAttribute(k_attn, cudaFuncAttributeMaxDynamicSharedMemorySize, K1_SMEM);
    cudaFuncSetAttribute(k3a_merge, cudaFuncAttributeMaxDynamicSharedMemorySize, K1_SMEM);
    cudaFuncSetAttribute(k3b_gru_out, cudaFuncAttributeMaxDynamicSharedMemorySize, K3B_SMEM);

    int nb = (NNODES + 63) / 64;
    k0_fold_attn<<<1, 128>>>(Wfc, al, ar);
    k1_node_linear<<<nb, 256, K1_SMEM>>>(x, Wm, bm);
    k2_aggregate<<<NNODES, 128>>>(x, srcp, Wg, bg);
    k_attn<<<dim3(nb, 2), 256, K1_SMEM>>>(Wfc);
    k3a_merge<<<nb, 256, K1_SMEM>>>(x, Wmg, bmg);
    k3b_gru_out<<<nb, 256, K3B_SMEM>>>(hin, Wih, Whh, bih, bhh, Wo, bo, out);
}

// round 5
// speedup vs baseline: 1.3502x; 1.0778x over previous
#include <cuda_runtime.h>
#include <math.h>

#define NNODES 50000
#define DEGC 16

// ---------------- scratch (device globals) ---------------------------------
__device__ float g_z[NNODES * 64];      // z = x@Wm+bm
__device__ float g_e[NNODES * 4];       // el0, el1, er0, er1
__device__ float g_xw[NNODES * 256];    // per-head alpha-weighted x sums [h][128]
__device__ float g_gate[NNODES * 2];    // gate per head
__device__ float g_vlr[128 * 4];        // [k][el0,el1,er0,er1]
__device__ float g_U[2 * 128 * 64];     // U_h = Wfc_h @ Wmerge2_h  [h][k][c]

__device__ __forceinline__ float sigmoidf_(float v) { return 1.f / (1.f + __expf(-v)); }

__device__ __forceinline__ unsigned f2tf(float v) {
    unsigned r;
    asm("cvt.rna.tf32.f32 %0, %1;" : "=r"(r) : "f"(v));
    return r;
}

__device__ __forceinline__ void mma_tf32(float c[4], unsigned a0, unsigned a1,
                                         unsigned a2, unsigned a3,
                                         unsigned b0, unsigned b1) {
    asm volatile(
        "mma.sync.aligned.m16n8k8.row.col.f32.tf32.tf32.f32 "
        "{%0,%1,%2,%3}, {%4,%5,%6,%7}, {%8,%9}, {%0,%1,%2,%3};"
        : "+f"(c[0]), "+f"(c[1]), "+f"(c[2]), "+f"(c[3])
        : "r"(a0), "r"(a1), "r"(a2), "r"(a3), "r"(b0), "r"(b1));
}

#define AS_STRIDE 140   // 64 rows x K=128
#define BS_STRIDE 72    // 128 k x 64 cols (8k+n conflict-free mod 32)
#define MS_STRIDE 76
#define K1_SMEM ((64 * AS_STRIDE + 128 * BS_STRIDE) * 4)   // 72704 B
// fused k3 smem (floats): xs@0 [64][140]=8960 | Bs@8960 [128][72]=9216 | ms@18176 [64][76]=4864
// stage-B aliases: hs@0 [64][76], nh@4864 [64][76], wt@9728 [64][72]
#define K3_SMEM ((64 * AS_STRIDE + 128 * BS_STRIDE + 64 * MS_STRIDE) * 4)  // 92160 B

// ---------------- K0a: fold attn vectors -----------------------------------
__global__ void k0_fold_attn(const float* __restrict__ Wfc,
                             const float* __restrict__ al,
                             const float* __restrict__ ar) {
    int k = threadIdx.x;  // 128
#pragma unroll
    for (int h = 0; h < 2; ++h) {
        float sl = 0.f, sr = 0.f;
#pragma unroll 8
        for (int q = 0; q < 64; ++q) {
            float w = Wfc[k * 128 + h * 64 + q];
            sl += w * al[h * 64 + q];
            sr += w * ar[h * 64 + q];
        }
        g_vlr[k * 4 + h] = sl;
        g_vlr[k * 4 + 2 + h] = sr;
    }
}

// ---------------- K0b: U_h = Wfc_h @ Wmerge2_h  (grid (128,2), block 64) ---
__global__ void k0_fold_U(const float* __restrict__ Wfc,
                          const float* __restrict__ Wmerge) {
    int k = blockIdx.x, h = blockIdx.y, c = threadIdx.x;
    float s = 0.f;
#pragma unroll 8
    for (int q = 0; q < 64; ++q)
        s += Wfc[k * 128 + h * 64 + q] * Wmerge[(128 + h * 64 + q) * 64 + c];
    g_U[(h * 128 + k) * 64 + c] = s;
}

// ---------------- K1: z = x@Wm+bm ; el/er tail (8 warps) -------------------
__global__ __launch_bounds__(256) void k1_node_linear(
    const float* __restrict__ x, const float* __restrict__ Wm,
    const float* __restrict__ bm) {
    extern __shared__ float sm[];
    float(*As)[AS_STRIDE] = (float(*)[AS_STRIDE])sm;
    float(*Bs)[BS_STRIDE] = (float(*)[BS_STRIDE])(sm + 64 * AS_STRIDE);
    const int tid = threadIdx.x, lane = tid & 31, wid = tid >> 5;
    const int n0 = blockIdx.x * 64;
    const int row0 = (wid >> 1) * 16 + (lane >> 2);
    const int colh = (wid & 1) * 32;
    const int kq = lane & 3;
    const int cn = lane >> 2;

    for (int idx = tid; idx < 64 * 128; idx += 256) {
        int nn = idx >> 7, k = idx & 127;
        int node = n0 + nn;
        float v = (node < NNODES) ? x[node * 128 + k] : 0.f;
        As[nn][k] = __uint_as_float(f2tf(v));
    }
    for (int idx = tid; idx < 128 * 64; idx += 256) {
        int k = idx >> 6, c = idx & 63;
        Bs[k][c] = __uint_as_float(f2tf(Wm[k * 64 + c]));
    }
    __syncthreads();

    float C[4][4];
#pragma unroll
    for (int nt = 0; nt < 4; ++nt)
#pragma unroll
        for (int e = 0; e < 4; ++e) C[nt][e] = 0.f;

#pragma unroll
    for (int ks = 0; ks < 16; ++ks) {
        int kb = ks * 8;
        unsigned a0 = __float_as_uint(As[row0][kb + kq]);
        unsigned a1 = __float_as_uint(As[row0 + 8][kb + kq]);
        unsigned a2 = __float_as_uint(As[row0][kb + kq + 4]);
        unsigned a3 = __float_as_uint(As[row0 + 8][kb + kq + 4]);
#pragma unroll
        for (int nt = 0; nt < 4; ++nt) {
            int col = colh + nt * 8 + cn;
            unsigned b0 = __float_as_uint(Bs[kb + kq][col]);
            unsigned b1 = __float_as_uint(Bs[kb + kq + 4][col]);
            mma_tf32(C[nt], a0, a1, a2, a3, b0, b1);
        }
    }

    int node0 = n0 + row0, node1 = node0 + 8;
#pragma unroll
    for (int nt = 0; nt < 4; ++nt) {
        int c0 = colh + nt * 8 + (lane & 3) * 2;
        float ba = bm[c0], bb = bm[c0 + 1];
        if (node0 < NNODES)
            *(float2*)&g_z[node0 * 64 + c0] = make_float2(C[nt][0] + ba, C[nt][1] + bb);
        if (node1 < NNODES)
            *(float2*)&g_z[node1 * 64 + c0] = make_float2(C[nt][2] + ba, C[nt][3] + bb);
    }

    __syncthreads();
    float* vs = (float*)Bs;
    for (int idx = tid; idx < 512; idx += 256) vs[idx] = g_vlr[idx];
    __syncthreads();
    {
        int nn = tid >> 2, c = tid & 3;
        float s = 0.f;
#pragma unroll 16
        for (int k = 0; k < 128; ++k) s += As[nn][k] * vs[k * 4 + c];
        int node = n0 + nn;
        if (node < NNODES) g_e[node * 4 + c] = s;
    }
}

// ---------------- K2: gather + softmax + weighted-x + gate -----------------
__global__ void k2_aggregate(const float* __restrict__ x,
                             const int* __restrict__ src,
                             const float* __restrict__ Wg,
                             const float* __restrict__ bg) {
    const int n = blockIdx.x;
    const int t = threadIdx.x;  // 128
    __shared__ int ssrc[16];
    __shared__ float se[2][16];
    __shared__ float salpha[2][16];
    __shared__ float red[128];

    if (t < 16) ssrc[t] = src[n * DEGC + t];
    __syncthreads();

    float val[16];
    float mean = 0.f;
#pragma unroll
    for (int j = 0; j < 16; ++j) {
        val[j] = x[ssrc[j] * 128 + t];
        mean += val[j];
    }
    mean *= (1.f / 16.f);

    float mz = -3.4e38f;
    if (t < 64) {
#pragma unroll
        for (int j = 0; j < 16; ++j) mz = fmaxf(mz, g_z[ssrc[j] * 64 + t]);
    }

    if (t < 32) {
        int j = t >> 1, h = t & 1;
        float e = g_e[ssrc[j] * 4 + h] + g_e[n * 4 + 2 + h];
        se[h][j] = (e > 0.f) ? e : 0.2f * e;
    }
    __syncthreads();

    if (t < 2) {
        float m = -3.4e38f;
#pragma unroll
        for (int j = 0; j < 16; ++j) m = fmaxf(m, se[t][j]);
        float ssum = 0.f;
#pragma unroll
        for (int j = 0; j < 16; ++j) {
            float v = __expf(se[t][j] - m);
            salpha[t][j] = v;
            ssum += v;
        }
        float inv = 1.f / fmaxf(ssum, 1e-12f);
#pragma unroll
        for (int j = 0; j < 16; ++j) salpha[t][j] *= inv;
    }
    __syncthreads();

    float xw0 = 0.f, xw1 = 0.f;
#pragma unroll
    for (int j = 0; j < 16; ++j) {
        xw0 += salpha[0][j] * val[j];
        xw1 += salpha[1][j] * val[j];
    }
    g_xw[n * 256 + t] = xw0;
    g_xw[n * 256 + 128 + t] = xw1;

    float xv = x[n * 128 + t];
    float p0 = xv * Wg[t * 2 + 0] + mean * Wg[(128 + t) * 2 + 0];
    float p1 = xv * Wg[t * 2 + 1] + mean * Wg[(128 + t) * 2 + 1];
    if (t < 64) {
        p0 += mz * Wg[(256 + t) * 2 + 0];
        p1 += mz * Wg[(256 + t) * 2 + 1];
    }
    red[t] = p0; __syncthreads();
    for (int o = 64; o > 0; o >>= 1) { if (t < o) red[t] += red[t + o]; __syncthreads(); }
    if (t == 0) g_gate[n * 2 + 0] = sigmoidf_(red[0] + bg[0]);
    __syncthreads();
    red[t] = p1; __syncthreads();
    for (int o = 64; o > 0; o >>= 1) { if (t < o) red[t] += red[t + o]; __syncthreads(); }
    if (t == 0) g_gate[n * 2 + 1] = sigmoidf_(red[0] + bg[1]);
}

// ---------------- K3 fused: meso (merge via U) + GRU + output --------------
__global__ __launch_bounds__(256) void k3_fused(
    const float* __restrict__ x, const float* __restrict__ Wmerge,
    const float* __restrict__ bmerge,
    const float* __restrict__ hin, const float* __restrict__ W_ih,
    const float* __restrict__ W_hh, const float* __restrict__ b_ih,
    const float* __restrict__ b_hh, const float* __restrict__ Wout,
    const float* __restrict__ bout, float* __restrict__ out) {
    extern __shared__ float sm[];
    float(*xs)[AS_STRIDE] = (float(*)[AS_STRIDE])sm;                    // stage A
    float(*Bs)[BS_STRIDE] = (float(*)[BS_STRIDE])(sm + 64 * AS_STRIDE); // stage A
    float(*ms)[MS_STRIDE] = (float(*)[MS_STRIDE])(sm + 64 * AS_STRIDE + 128 * BS_STRIDE);
    // stage B aliases (over dead xs/Bs region)
    float(*hs)[MS_STRIDE] = (float(*)[MS_STRIDE])sm;
    float(*nh)[MS_STRIDE] = (float(*)[MS_STRIDE])(sm + 64 * MS_STRIDE);
    float(*wt)[BS_STRIDE] = (float(*)[BS_STRIDE])(sm + 2 * 64 * MS_STRIDE);

    const int tid = threadIdx.x, lane = tid & 31, wid = tid >> 5;
    const int n0 = blockIdx.x * 64;
    const int row0 = (wid >> 1) * 16 + (lane >> 2);
    const int colh = (wid & 1) * 32;
    const int kq = lane & 3;
    const int cn = lane >> 2;
    const int node0 = n0 + row0, node1 = node0 + 8;

    // ---------------- stage A: meso = x@W1 + Σ_h gate_h·(xw_h@U_h) + bmerge
    float Cm[4][4];
#pragma unroll
    for (int nt = 0; nt < 4; ++nt)
#pragma unroll
        for (int e = 0; e < 4; ++e) Cm[nt][e] = 0.f;

    for (int pass = 0; pass < 3; ++pass) {
        __syncthreads();
        // A tile: x, xw0, xw1
        for (int idx = tid; idx < 64 * 128; idx += 256) {
            int nn = idx >> 7, k = idx & 127;
            int node = n0 + nn;
            float v = 0.f;
            if (node < NNODES)
                v = (pass == 0) ? x[node * 128 + k]
                                : g_xw[node * 256 + (pass - 1) * 128 + k];
            xs[nn][k] = __uint_as_float(f2tf(v));
        }
        // B tile: W1 (=Wmerge rows 0..127), U0, U1
        for (int idx = tid; idx < 128 * 64; idx += 256) {
            int k = idx >> 6, c = idx & 63;
            float w = (pass == 0) ? Wmerge[k * 64 + c]
                                  : g_U[((pass - 1) * 128 + k) * 64 + c];
            Bs[k][c] = __uint_as_float(f2tf(w));
        }
        __syncthreads();

        float C[4][4];
#pragma unroll
        for (int nt = 0; nt < 4; ++nt)
#pragma unroll
            for (int e = 0; e < 4; ++e) C[nt][e] = 0.f;

#pragma unroll
        for (int ks = 0; ks < 16; ++ks) {
            int kb = ks * 8;
            unsigned a0 = __float_as_uint(xs[row0][kb + kq]);
            unsigned a1 = __float_as_uint(xs[row0 + 8][kb + kq]);
            unsigned a2 = __float_as_uint(xs[row0][kb + kq + 4]);
            unsigned a3 = __float_as_uint(xs[row0 + 8][kb + kq + 4]);
#pragma unroll
            for (int nt = 0; nt < 4; ++nt) {
                int col = colh + nt * 8 + cn;
                unsigned b0 = __float_as_uint(Bs[kb + kq][col]);
                unsigned b1 = __float_as_uint(Bs[kb + kq + 4][col]);
                mma_tf32(C[nt], a0, a1, a2, a3, b0, b1);
            }
        }

        if (pass == 0) {
#pragma unroll
            for (int nt = 0; nt < 4; ++nt)
#pragma unroll
                for (int e = 0; e < 4; ++e) Cm[nt][e] += C[nt][e];
        } else {
            int h = pass - 1;
            float g0 = (node0 < NNODES) ? g_gate[node0 * 2 + h] : 0.f;
            float g1 = (node1 < NNODES) ? g_gate[node1 * 2 + h] : 0.f;
#pragma unroll
            for (int nt = 0; nt < 4; ++nt) {
                Cm[nt][0] += g0 * C[nt][0];
                Cm[nt][1] += g0 * C[nt][1];
                Cm[nt][2] += g1 * C[nt][2];
                Cm[nt][3] += g1 * C[nt][3];
            }
        }
    }
    __syncthreads();  // xs/Bs now dead; ms region safe to fill

    // write meso (tf32) into ms
#pragma unroll
    for (int nt = 0; nt < 4; ++nt) {
        int c0 = colh + nt * 8 + (lane & 3) * 2;
        float ba = bmerge[c0], bb = bmerge[c0 + 1];
        ms[row0][c0]     = __uint_as_float(f2tf(Cm[nt][0] + ba));
        ms[row0][c0 + 1] = __uint_as_float(f2tf(Cm[nt][1] + bb));
        ms[row0 + 8][c0]     = __uint_as_float(f2tf(Cm[nt][2] + ba));
        ms[row0 + 8][c0 + 1] = __uint_as_float(f2tf(Cm[nt][3] + bb));
    }

    // load h tile (raw fp32)
    for (int idx = tid; idx < 64 * 64; idx += 256) {
        int nn = idx >> 6, k = idx & 63;
        int node = n0 + nn;
        hs[nn][k] = (node < NNODES) ? hin[node * 64 + k] : 0.f;
    }

    // ---------------- stage B: GRU gates ------------------------------------
    float rr[4][4], zz[4][4];
    for (int g = 0; g < 3; ++g) {
        float ai[4][4], ah[4][4];
        // --- ih GEMM
        __syncthreads();
        for (int idx = tid; idx < 64 * 64; idx += 256) {
            int c = idx >> 6, k = idx & 63;
            wt[k][c] = __uint_as_float(f2tf(W_ih[(g * 64 + c) * 64 + k]));
        }
        __syncthreads();
#pragma unroll
        for (int nt = 0; nt < 4; ++nt)
#pragma unroll
            for (int e = 0; e < 4; ++e) ai[nt][e] = 0.f;
#pragma unroll
        for (int ks = 0; ks < 8; ++ks) {
            int kb = ks * 8;
            unsigned a0 = __float_as_uint(ms[row0][kb + kq]);
            unsigned a1 = __float_as_uint(ms[row0 + 8][kb + kq]);
            unsigned a2 = __float_as_uint(ms[row0][kb + kq + 4]);
            unsigned a3 = __float_as_uint(ms[row0 + 8][kb + kq + 4]);
#pragma unroll
            for (int nt = 0; nt < 4; ++nt) {
                int col = colh + nt * 8 + cn;
                unsigned b0 = __float_as_uint(wt[kb + kq][col]);
                unsigned b1 = __float_as_uint(wt[kb + kq + 4][col]);
                mma_tf32(ai[nt], a0, a1, a2, a3, b0, b1);
            }
        }
        // --- hh GEMM
        __syncthreads();
        for (int idx = tid; idx < 64 * 64; idx += 256) {
            int c = idx >> 6, k = idx & 63;
            wt[k][c] = __uint_as_float(f2tf(W_hh[(g * 64 + c) * 64 + k]));
        }
        __syncthreads();
#pragma unroll
        for (int nt = 0; nt < 4; ++nt)
#pragma unroll
            for (int e = 0; e < 4; ++e) ah[nt][e] = 0.f;
#pragma unroll
        for (int ks = 0; ks < 8; ++ks) {
            int kb = ks * 8;
            unsigned h0 = __float_as_uint(hs[row0][kb + kq]);
            unsigned h1 = __float_as_uint(hs[row0 + 8][kb + kq]);
            unsigned h2 = __float_as_uint(hs[row0][kb + kq + 4]);
            unsigned h3 = __float_as_uint(hs[row0 + 8][kb + kq + 4]);
#pragma unroll
            for (int nt = 0; nt < 4; ++nt) {
                int col = colh + nt * 8 + cn;
                unsigned b0 = __float_as_uint(wt[kb + kq][col]);
                unsigned b1 = __float_as_uint(wt[kb + kq + 4][col]);
                mma_tf32(ah[nt], h0, h1, h2, h3, b0, b1);
            }
        }

#pragma unroll
        for (int nt = 0; nt < 4; ++nt) {
#pragma unroll
            for (int e = 0; e < 4; ++e) {
                int c = colh + nt * 8 + (lane & 3) * 2 + (e & 1);
                int r = row0 + (e >> 1) * 8;
                float gi = ai[nt][e] + b_ih[g * 64 + c];
                float gh = ah[nt][e] + b_hh[g * 64 + c];
                if (g == 0) {
                    rr[nt][e] = sigmoidf_(gi + gh);
                } else if (g == 1) {
                    zz[nt][e] = sigmoidf_(gi + gh);
                } else {
                    float ng = tanhf(gi + rr[nt][e] * gh);
                    float hv = hs[r][c];
                    float v = (1.f - zz[nt][e]) * ng + zz[nt][e] * hv;
                    int node = n0 + r;
                    if (node < NNODES)
                        out[(size_t)NNODES * 64 + (size_t)node * 64 + c] = v;
                    nh[r][c] = __uint_as_float(f2tf(v));
                }
            }
        }
    }

    // ---------------- output projection: source = nh@Wout + bout -----------
    __syncthreads();
    for (int idx = tid; idx < 64 * 64; idx += 256) {
        int k = idx >> 6, c = idx & 63;
        wt[k][c] = __uint_as_float(f2tf(Wout[k * 64 + c]));
    }
    __syncthreads();

    float C[4][4];
#pragma unroll
    for (int nt = 0; nt < 4; ++nt)
#pragma unroll
        for (int e = 0; e < 4; ++e) C[nt][e] = 0.f;
#pragma unroll
    for (int ks = 0; ks < 8; ++ks) {
        int kb = ks * 8;
        unsigned a0 = __float_as_uint(nh[row0][kb + kq]);
        unsigned a1 = __float_as_uint(nh[row0 + 8][kb + kq]);
        unsigned a2 = __float_as_uint(nh[row0][kb + kq + 4]);
        unsigned a3 = __float_as_uint(nh[row0 + 8][kb + kq + 4]);
#pragma unroll
        for (int nt = 0; nt < 4; ++nt) {
            int col = colh + nt * 8 + cn;
            unsigned b0 = __float_as_uint(wt[kb + kq][col]);
            unsigned b1 = __float_as_uint(wt[kb + kq + 4][col]);
            mma_tf32(C[nt], a0, a1, a2, a3, b0, b1);
        }
    }
#pragma unroll
    for (int nt = 0; nt < 4; ++nt) {
        int c0 = colh + nt * 8 + (lane & 3) * 2;
        float ba = bout[c0], bb = bout[c0 + 1];
        if (node0 < NNODES)
            *(float2*)&out[(size_t)node0 * 64 + c0] = make_float2(C[nt][0] + ba, C[nt][1] + bb);
        if (node1 < NNODES)
            *(float2*)&out[(size_t)node1 * 64 + c0] = make_float2(C[nt][2] + ba, C[nt][3] + bb);
    }
}

// ---------------- launch ---------------------------------------------------
extern "C" void kernel_launch(void* const* d_in, const int* in_sizes, int n_in,
                              void* d_out, int out_size) {
    const float* x    = (const float*)d_in[0];
    const float* hin  = (const float*)d_in[1];
    const int*   srcp = (const int*)d_in[2];
    const float* Wm   = (const float*)d_in[4];
    const float* bm   = (const float*)d_in[5];
    const float* Wg   = (const float*)d_in[6];
    const float* bg   = (const float*)d_in[7];
    const float* Wfc  = (const float*)d_in[8];
    const float* al   = (const float*)d_in[9];
    const float* ar   = (const float*)d_in[10];
    const float* Wmg  = (const float*)d_in[11];
    const float* bmg  = (const float*)d_in[12];
    const float* Wih  = (const float*)d_in[13];
    const float* Whh  = (const float*)d_in[14];
    const float* bih  = (const float*)d_in[15];
    const float* bhh  = (const float*)d_in[16];
    const float* Wo   = (const float*)d_in[17];
    const float* bo   = (const float*)d_in[18];
    float* out = (float*)d_out;

    cudaFuncSetAttribute(k1_node_linear, cudaFuncAttributeMaxDynamicSharedMemorySize, K1_SMEM);
    cudaFuncSetAttribute(k3_fused, cudaFuncAttributeMaxDynamicSharedMemorySize, K3_SMEM);

    int nb = (NNODES + 63) / 64;
    k0_fold_attn<<<1, 128>>>(Wfc, al, ar);
    k0_fold_U<<<dim3(128, 2), 64>>>(Wfc, Wmg);
    k1_node_linear<<<nb, 256, K1_SMEM>>>(x, Wm, bm);
    k2_aggregate<<<NNODES, 128>>>(x, srcp, Wg, bg);
    k3_fused<<<nb, 256, K3_SMEM>>>(x, Wmg, bmg, hin, Wih, Whh, bih, bhh, Wo, bo, out);
}